// round 3
// baseline (speedup 1.0000x reference)
#include <cuda_runtime.h>
#include <cuda_bf16.h>

// Problem constants (fixed by the dataset):
//   e_src: (16, 1024, 8, 256) fp32
//   d_src: (16, 128) int32  (jax randint silently downgrades int64->int32
//                            under default jax config)
//   output: (8, 128, 256) fp32
#define BH 8
#define TT 1024
#define FF 8
#define SS 128
#define CC 256
#define C4 (CC / 4)

// One block per (b, s). 256 threads = 4 groups x 64 lanes.
// Each lane owns 4 channels (float4). Group g sums rows k = g, g+4, ...
// over the contiguous chunk of n = (end-start)*F rows of 256 floats.
__global__ void __launch_bounds__(256) agg_kernel(const float* __restrict__ e,
                                                  const int* __restrict__ dsrc,
                                                  float* __restrict__ out) {
    const int s = blockIdx.x;
    const int b = blockIdx.y;
    const int tid = threadIdx.x;
    const int c4 = tid & 63;
    const int g  = tid >> 6;

    // --- load this batch's 128 durations; off = sum_{i<s} d[i] ---
    __shared__ int sd[SS];
    __shared__ int wsum[8];
    if (tid < SS) sd[tid] = dsrc[b * SS + tid];
    __syncthreads();

    int part = (tid < s) ? sd[tid] : 0;   // tid < s < 128 implies in-range
    #pragma unroll
    for (int o = 16; o > 0; o >>= 1)
        part += __shfl_down_sync(0xffffffffu, part, o);
    if ((tid & 31) == 0) wsum[tid >> 5] = part;
    __syncthreads();

    const int off = wsum[0] + wsum[1] + wsum[2] + wsum[3] +
                    wsum[4] + wsum[5] + wsum[6] + wsum[7];
    const int dv  = sd[s];
    const int start = min(off, TT);
    const int end   = min(off + dv, TT);
    const int n = (end - start) * FF;  // number of 256-float rows (<= 120)

    const float4* __restrict__ p =
        (const float4*)e + ((size_t)b * TT * FF + (size_t)start * FF) * C4 +
        (size_t)g * C4 + c4;

    float4 acc = make_float4(0.f, 0.f, 0.f, 0.f);
    for (int k = g; k < n; k += 4) {
        float4 v = *p;
        p += 4 * C4;
        acc.x += v.x; acc.y += v.y; acc.z += v.z; acc.w += v.w;
    }

    __shared__ float4 red[256];
    red[tid] = acc;
    __syncthreads();

    if (g == 0) {
        float4 a0 = red[c4];
        float4 a1 = red[64 + c4];
        float4 a2 = red[128 + c4];
        float4 a3 = red[192 + c4];
        const float inv = (dv > 0) ? (1.0f / (float)(dv * FF)) : 0.0f;
        float4 r;
        r.x = (a0.x + a1.x + a2.x + a3.x) * inv;
        r.y = (a0.y + a1.y + a2.y + a3.y) * inv;
        r.z = (a0.z + a1.z + a2.z + a3.z) * inv;
        r.w = (a0.w + a1.w + a2.w + a3.w) * inv;
        ((float4*)out)[((size_t)b * SS + s) * C4 + c4] = r;
    }
}

extern "C" void kernel_launch(void* const* d_in, const int* in_sizes, int n_in,
                              void* d_out, int out_size) {
    // e_src is the large tensor (33,554,432 elems); d_src is 2048 elems.
    int ei = 0, di = 1;
    if (n_in >= 2 && in_sizes[0] < in_sizes[1]) { ei = 1; di = 0; }

    const float* e = (const float*)d_in[ei];   // (16,1024,8,256) fp32
    const int*   d = (const int*)d_in[di];     // (16,128) int32
    float* out = (float*)d_out;                // (8,128,256) fp32

    dim3 grid(SS, BH);
    agg_kernel<<<grid, 256>>>(e, d, out);
}